// round 1
// baseline (speedup 1.0000x reference)
#include <cuda_runtime.h>
#include <cuda_bf16.h>

#define NA 500000
#define NM 100000
#define EDG 1000000
#define FIN 32
#define HH 64

// ---------------- scratch (device globals: no allocation in kernel_launch) ----------------
__device__ float g_deg_acc[NA];
__device__ float g_deg_mer[NM];
__device__ float g_sum_a32[(size_t)NA * FIN];   //  64 MB
__device__ float g_sum_m32[(size_t)NM * FIN];   // 12.8 MB
__device__ float g_sum_a64[(size_t)NA * HH];    // 128 MB
__device__ float g_sum_m64[(size_t)NM * HH];    // 25.6 MB
__device__ float g_acc1[(size_t)NA * HH];       // 128 MB
__device__ float g_mer1[(size_t)NM * HH];       // 25.6 MB
__device__ float g_pa[(size_t)NA * HH];         // 128 MB  (acc2 @ W1_top)
__device__ float g_pm[(size_t)NM * HH];         // 25.6 MB (mer2 @ W1_bot + b1)

// ---------------- degree counts ----------------
__global__ void degree_kernel(const int* __restrict__ src, const int* __restrict__ dst,
                              float* __restrict__ dacc, float* __restrict__ dmer, int E) {
    int i = blockIdx.x * blockDim.x + threadIdx.x;
    if (i < E) {
        atomicAdd(&dacc[src[i]], 1.0f);
        atomicAdd(&dmer[dst[i]], 1.0f);
    }
}

// ---------------- scatter-add: sum[to[e]*K + f] += xin[from[e]*K + f] ----------------
template <int K>
__global__ void scatter_kernel(const int* __restrict__ efrom, const int* __restrict__ eto,
                               const float* __restrict__ xin, float* __restrict__ sum, int E) {
    int gw  = (blockIdx.x * blockDim.x + threadIdx.x) >> 5;
    int lid = threadIdx.x & 31;
    if (gw >= E) return;
    int s = efrom[gw];
    int d = eto[gw];
    const float* xs = xin + (size_t)s * K;
    float*       sd = sum + (size_t)d * K;
#pragma unroll
    for (int r = 0; r < K / 32; r++) {
        float v = xs[r * 32 + lid];
        atomicAdd(&sd[r * 32 + lid], v);
    }
}

// ---------------- node SAGE kernel ----------------
// out = relu(mean @ wl + bl + xin @ wr)            (FUSE=false)
// out = relu(...) @ wp + bp                        (FUSE=true; acc2/mer2 never stored)
// Weights in smem, pair-permuted: s[k*64 + 2*c + h] = w[k*64 + c + 32*h], c<32,h<2
// so each lane float2-loads its (col lid, col lid+32) pair. 2 nodes per warp.
template <int K, bool FUSE>
__global__ void node_kernel(const float* __restrict__ sum, const float* __restrict__ deg,
                            const float* __restrict__ xin,
                            const float* __restrict__ wl, const float* __restrict__ bl,
                            const float* __restrict__ wr,
                            const float* __restrict__ wp, const float* __restrict__ bp,
                            float* __restrict__ out, int N) {
    extern __shared__ float smw[];
    float* s_wl = smw;               // K*64
    float* s_wr = smw + K * 64;      // K*64
    float* s_wp = smw + 2 * K * 64;  // 64*64 when FUSE

    for (int i = threadIdx.x; i < K * 64; i += blockDim.x) {
        int k = i >> 6, c = i & 63;
        int di = (k << 6) + ((c & 31) << 1) + (c >> 5);
        s_wl[di] = wl[i];
        s_wr[di] = wr[i];
    }
    if (FUSE) {
        for (int i = threadIdx.x; i < 64 * 64; i += blockDim.x) {
            int k = i >> 6, c = i & 63;
            s_wp[(k << 6) + ((c & 31) << 1) + (c >> 5)] = wp[i];
        }
    }
    __syncthreads();

    int lid = threadIdx.x & 31;
    int gw  = (blockIdx.x * blockDim.x + threadIdx.x) >> 5;
    int nw  = (gridDim.x * blockDim.x) >> 5;

    float bl0 = bl[lid], bl1 = bl[lid + 32];
    float bp0 = 0.f, bp1 = 0.f;
    if (FUSE && bp != nullptr) { bp0 = bp[lid]; bp1 = bp[lid + 32]; }

    for (int n0 = gw * 2; n0 < N; n0 += nw * 2) {
        int n1 = n0 + 1;  // NA, NM are even
        float i0 = 1.0f / fmaxf(deg[n0], 1.0f);
        float i1 = 1.0f / fmaxf(deg[n1], 1.0f);

        const float* su0 = sum + (size_t)n0 * K;
        const float* su1 = sum + (size_t)n1 * K;
        const float* xi0 = xin + (size_t)n0 * K;
        const float* xi1 = xin + (size_t)n1 * K;

        float m0a = su0[lid] * i0, m1a = su1[lid] * i1;
        float x0a = xi0[lid],      x1a = xi1[lid];
        float m0b = 0.f, m1b = 0.f, x0b = 0.f, x1b = 0.f;
        if (K == 64) {
            m0b = su0[32 + lid] * i0; m1b = su1[32 + lid] * i1;
            x0b = xi0[32 + lid];      x1b = xi1[32 + lid];
        }

        float o00 = bl0, o01 = bl1, o10 = bl0, o11 = bl1;
#pragma unroll
        for (int k = 0; k < 32; k++) {
            float2 wlv = *(const float2*)&s_wl[(k << 6) + (lid << 1)];
            float2 wrv = *(const float2*)&s_wr[(k << 6) + (lid << 1)];
            float a0 = __shfl_sync(0xffffffffu, m0a, k);
            float a1 = __shfl_sync(0xffffffffu, m1a, k);
            float b0 = __shfl_sync(0xffffffffu, x0a, k);
            float b1 = __shfl_sync(0xffffffffu, x1a, k);
            o00 += a0 * wlv.x; o01 += a0 * wlv.y;
            o00 += b0 * wrv.x; o01 += b0 * wrv.y;
            o10 += a1 * wlv.x; o11 += a1 * wlv.y;
            o10 += b1 * wrv.x; o11 += b1 * wrv.y;
        }
        if (K == 64) {
#pragma unroll
            for (int k = 0; k < 32; k++) {
                float2 wlv = *(const float2*)&s_wl[((32 + k) << 6) + (lid << 1)];
                float2 wrv = *(const float2*)&s_wr[((32 + k) << 6) + (lid << 1)];
                float a0 = __shfl_sync(0xffffffffu, m0b, k);
                float a1 = __shfl_sync(0xffffffffu, m1b, k);
                float b0 = __shfl_sync(0xffffffffu, x0b, k);
                float b1 = __shfl_sync(0xffffffffu, x1b, k);
                o00 += a0 * wlv.x; o01 += a0 * wlv.y;
                o00 += b0 * wrv.x; o01 += b0 * wrv.y;
                o10 += a1 * wlv.x; o11 += a1 * wlv.y;
                o10 += b1 * wrv.x; o11 += b1 * wrv.y;
            }
        }
        o00 = fmaxf(o00, 0.f); o01 = fmaxf(o01, 0.f);
        o10 = fmaxf(o10, 0.f); o11 = fmaxf(o11, 0.f);

        float* ot0 = out + (size_t)n0 * 64;
        float* ot1 = out + (size_t)n1 * 64;
        if (!FUSE) {
            ot0[lid] = o00; ot0[32 + lid] = o01;
            ot1[lid] = o10; ot1[32 + lid] = o11;
        } else {
            float p00 = bp0, p01 = bp1, p10 = bp0, p11 = bp1;
#pragma unroll
            for (int k = 0; k < 32; k++) {
                float2 wv  = *(const float2*)&s_wp[(k << 6) + (lid << 1)];
                float2 wv2 = *(const float2*)&s_wp[((32 + k) << 6) + (lid << 1)];
                float v0 = __shfl_sync(0xffffffffu, o00, k);
                float v1 = __shfl_sync(0xffffffffu, o10, k);
                float u0 = __shfl_sync(0xffffffffu, o01, k);
                float u1 = __shfl_sync(0xffffffffu, o11, k);
                p00 += v0 * wv.x;  p01 += v0 * wv.y;
                p10 += v1 * wv.x;  p11 += v1 * wv.y;
                p00 += u0 * wv2.x; p01 += u0 * wv2.y;
                p10 += u1 * wv2.x; p11 += u1 * wv2.y;
            }
            ot0[lid] = p00; ot0[32 + lid] = p01;
            ot1[lid] = p10; ot1[32 + lid] = p11;
        }
    }
}

// ---------------- edge scorer: logit = relu(pa[src] + pm[dst]) . w2 + b2 ----------------
__global__ void edge_kernel(const int* __restrict__ src, const int* __restrict__ dst,
                            const float* __restrict__ pa, const float* __restrict__ pm,
                            const float* __restrict__ w2, const float* __restrict__ b2,
                            float* __restrict__ out, int E) {
    int gw  = (blockIdx.x * blockDim.x + threadIdx.x) >> 5;
    int lid = threadIdx.x & 31;
    if (gw >= E) return;
    int s = src[gw];
    int d = dst[gw];
    float2 A = ((const float2*)pa)[(size_t)s * 32 + lid];
    float2 M = ((const float2*)pm)[(size_t)d * 32 + lid];
    float2 W = ((const float2*)w2)[lid];
    float h0 = fmaxf(A.x + M.x, 0.f);
    float h1 = fmaxf(A.y + M.y, 0.f);
    float p  = h0 * W.x + h1 * W.y;
    p += __shfl_xor_sync(0xffffffffu, p, 16);
    p += __shfl_xor_sync(0xffffffffu, p, 8);
    p += __shfl_xor_sync(0xffffffffu, p, 4);
    p += __shfl_xor_sync(0xffffffffu, p, 2);
    p += __shfl_xor_sync(0xffffffffu, p, 1);
    if (lid == 0) out[gw] = p + b2[0];
}

// ---------------- launch ----------------
extern "C" void kernel_launch(void* const* d_in, const int* in_sizes, int n_in,
                              void* d_out, int out_size) {
    const float* x_account  = (const float*)d_in[0];
    const float* x_merchant = (const float*)d_in[1];
    const int*   src        = (const int*)d_in[2];
    const int*   dst        = (const int*)d_in[3];
    const float* w1_am_l = (const float*)d_in[4];
    const float* b1_am_l = (const float*)d_in[5];
    const float* w1_am_r = (const float*)d_in[6];
    const float* w1_ma_l = (const float*)d_in[7];
    const float* b1_ma_l = (const float*)d_in[8];
    const float* w1_ma_r = (const float*)d_in[9];
    const float* w2_am_l = (const float*)d_in[10];
    const float* b2_am_l = (const float*)d_in[11];
    const float* w2_am_r = (const float*)d_in[12];
    const float* w2_ma_l = (const float*)d_in[13];
    const float* b2_ma_l = (const float*)d_in[14];
    const float* w2_ma_r = (const float*)d_in[15];
    const float* mlp_w1  = (const float*)d_in[16];   // [128,64] row-major
    const float* mlp_b1  = (const float*)d_in[17];
    const float* mlp_w2  = (const float*)d_in[18];
    const float* mlp_b2  = (const float*)d_in[19];
    float* out = (float*)d_out;

    void *p_deg_acc, *p_deg_mer, *p_sa32, *p_sm32, *p_sa64, *p_sm64;
    void *p_acc1, *p_mer1, *p_pa, *p_pm;
    cudaGetSymbolAddress(&p_deg_acc, g_deg_acc);
    cudaGetSymbolAddress(&p_deg_mer, g_deg_mer);
    cudaGetSymbolAddress(&p_sa32, g_sum_a32);
    cudaGetSymbolAddress(&p_sm32, g_sum_m32);
    cudaGetSymbolAddress(&p_sa64, g_sum_a64);
    cudaGetSymbolAddress(&p_sm64, g_sum_m64);
    cudaGetSymbolAddress(&p_acc1, g_acc1);
    cudaGetSymbolAddress(&p_mer1, g_mer1);
    cudaGetSymbolAddress(&p_pa, g_pa);
    cudaGetSymbolAddress(&p_pm, g_pm);

    cudaMemsetAsync(p_deg_acc, 0, (size_t)NA * 4, 0);
    cudaMemsetAsync(p_deg_mer, 0, (size_t)NM * 4, 0);
    cudaMemsetAsync(p_sm32, 0, (size_t)NM * FIN * 4, 0);
    cudaMemsetAsync(p_sa32, 0, (size_t)NA * FIN * 4, 0);
    cudaMemsetAsync(p_sm64, 0, (size_t)NM * HH * 4, 0);
    cudaMemsetAsync(p_sa64, 0, (size_t)NA * HH * 4, 0);

    degree_kernel<<<(EDG + 255) / 256, 256>>>(src, dst, (float*)p_deg_acc, (float*)p_deg_mer, EDG);

    // layer 1 aggregation (FIN=32)
    scatter_kernel<32><<<EDG / 8, 256>>>(src, dst, x_account, (float*)p_sm32, EDG);
    scatter_kernel<32><<<EDG / 8, 256>>>(dst, src, x_merchant, (float*)p_sa32, EDG);

    // layer 1 node transforms
    node_kernel<32, false><<<1184, 256, 2 * 32 * 64 * 4>>>(
        (const float*)p_sm32, (const float*)p_deg_mer, x_merchant,
        w1_am_l, b1_am_l, w1_am_r, nullptr, nullptr, (float*)p_mer1, NM);
    node_kernel<32, false><<<1184, 256, 2 * 32 * 64 * 4>>>(
        (const float*)p_sa32, (const float*)p_deg_acc, x_account,
        w1_ma_l, b1_ma_l, w1_ma_r, nullptr, nullptr, (float*)p_acc1, NA);

    // layer 2 aggregation (H=64)
    scatter_kernel<64><<<EDG / 8, 256>>>(src, dst, (const float*)p_acc1, (float*)p_sm64, EDG);
    scatter_kernel<64><<<EDG / 8, 256>>>(dst, src, (const float*)p_mer1, (float*)p_sa64, EDG);

    // layer 2 node transforms, fused with edge-MLP projection:
    //   pm = relu(sage_mer2) @ mlp_w1[64:128] + mlp_b1
    //   pa = relu(sage_acc2) @ mlp_w1[0:64]
    node_kernel<64, true><<<592, 256, 3 * 64 * 64 * 4>>>(
        (const float*)p_sm64, (const float*)p_deg_mer, (const float*)p_mer1,
        w2_am_l, b2_am_l, w2_am_r, mlp_w1 + 64 * 64, mlp_b1, (float*)p_pm, NM);
    node_kernel<64, true><<<592, 256, 3 * 64 * 64 * 4>>>(
        (const float*)p_sa64, (const float*)p_deg_acc, (const float*)p_acc1,
        w2_ma_l, b2_ma_l, w2_ma_r, mlp_w1, nullptr, (float*)p_pa, NA);

    // edge scorer
    edge_kernel<<<EDG / 8, 256>>>(src, dst, (const float*)p_pa, (const float*)p_pm,
                                  mlp_w2, mlp_b2, out, EDG);
}

// round 3
// speedup vs baseline: 1.5718x; 1.5718x over previous
#include <cuda_runtime.h>
#include <cuda_bf16.h>

#define NA 500000
#define NM 100000
#define EDG 1000000
#define FIN 32
#define HH 64

// ---------------- scratch ----------------
__device__ float g_deg_acc[NA];
__device__ float g_deg_mer[NM];
__device__ float g_sum_a32[(size_t)NA * FIN];
__device__ float g_sum_m32[(size_t)NM * FIN];
__device__ float g_sum_a64[(size_t)NA * HH];
__device__ float g_sum_m64[(size_t)NM * HH];
__device__ float g_acc1[(size_t)NA * HH];
__device__ float g_mer1[(size_t)NM * HH];
__device__ float g_pa[(size_t)NA * HH];
__device__ float g_pm[(size_t)NM * HH];

// ---------------- scatter-add with vector RED ----------------
// sum[eto[e]] += xin[efrom[e]] (row of K floats), via red.global.add.v4.f32.
// L = K/4 lanes per edge, 32/L edges per warp. Optionally counts degree of eto.
template <int K, bool DEG>
__global__ __launch_bounds__(256) void scatter_kernel(
    const int* __restrict__ efrom, const int* __restrict__ eto,
    const float* __restrict__ xin, float* __restrict__ sum,
    float* __restrict__ deg, int E) {
    constexpr int L = K / 4;
    constexpr int EPW = 32 / L;
    int t   = blockIdx.x * blockDim.x + threadIdx.x;
    int gw  = t >> 5;
    int lid = t & 31;
    int sub = lid / L;
    int off = lid % L;
    int e = gw * EPW + sub;
    if (e >= E) return;
    int s = __ldg(&efrom[e]);
    int d = __ldg(&eto[e]);
    float4 v = __ldg((const float4*)(xin + (size_t)s * K) + off);
    float* sd = sum + (size_t)d * K + off * 4;
    asm volatile("red.global.add.v4.f32 [%0], {%1,%2,%3,%4};"
                 :: "l"(sd), "f"(v.x), "f"(v.y), "f"(v.z), "f"(v.w) : "memory");
    if (DEG && off == 0) atomicAdd(&deg[d], 1.0f);
}

// ---------------- node SAGE kernel v2 (smem feature staging, 4 nodes/warp) ----------------
// o = relu(mean @ wl + bl + xin @ wr);  out = FUSE ? o @ wp + bp : o
// Weights pair-permuted in smem: s[k*64 + 2*c + h] holds w[k][c + 32*h], c<32, h<2.
// Features staged per-warp in smem interleaved (mean,x) float2 pairs -> broadcast LDS.
template <int K, bool FUSE>
__global__ __launch_bounds__(256) void node_kernel(
    const float* __restrict__ sum, const float* __restrict__ deg,
    const float* __restrict__ xin,
    const float* __restrict__ wl, const float* __restrict__ bl,
    const float* __restrict__ wr,
    const float* __restrict__ wp, const float* __restrict__ bp,
    float* __restrict__ out, int N) {
    extern __shared__ float smw[];
    float* s_wl = smw;                               // K*64
    float* s_wr = smw + K * 64;                      // K*64
    float* s_wp = smw + 2 * K * 64;                  // 64*64 if FUSE
    float* s_dyn = s_wp + (FUSE ? 64 * 64 : 0);      // 8 warps * 4 nodes * K * 2
    int wid = threadIdx.x >> 5;
    int lid = threadIdx.x & 31;
    float* s_feat = s_dyn + wid * (4 * K * 2);
    float* s_o    = s_feat;                          // aliased: o written after feat consumed

    for (int i = threadIdx.x; i < K * 64; i += blockDim.x) {
        int k = i >> 6, c = i & 63;
        int di = (k << 6) + ((c & 31) << 1) + (c >> 5);
        s_wl[di] = wl[i];
        s_wr[di] = wr[i];
    }
    if (FUSE) {
        for (int i = threadIdx.x; i < 64 * 64; i += blockDim.x) {
            int k = i >> 6, c = i & 63;
            s_wp[(k << 6) + ((c & 31) << 1) + (c >> 5)] = wp[i];
        }
    }
    __syncthreads();

    int gw = (blockIdx.x * blockDim.x + threadIdx.x) >> 5;
    int nw = (gridDim.x * blockDim.x) >> 5;

    float bl0 = bl[lid], bl1 = bl[lid + 32];
    float bp0 = 0.f, bp1 = 0.f;
    if (FUSE && bp != nullptr) { bp0 = bp[lid]; bp1 = bp[lid + 32]; }

    int j = lid >> 3, q = lid & 7;   // lane's staging node / quarter

    for (int n0 = gw * 4; n0 < N; n0 += nw * 4) {
        // ---- phase A: stage 4 nodes' (mean, x) into smem ----
        float dg = 1.0f;
        if (lid < 4 && n0 + lid < N) dg = deg[n0 + lid];
        float inv_all = 1.0f / fmaxf(dg, 1.0f);
        float inv = __shfl_sync(0xffffffffu, inv_all, j);
        int nj = n0 + j;
        if (nj < N) {
            const float4* su = (const float4*)(sum + (size_t)nj * K);
            const float4* xi = (const float4*)(xin + (size_t)nj * K);
            float2* fd = (float2*)&s_feat[j * (K * 2)];
#pragma unroll
            for (int r = 0; r < K / 32; r++) {
                int idx = q + r * 8;
                float4 sv = __ldg(&su[idx]);
                float4 xv = __ldg(&xi[idx]);
                fd[idx * 4 + 0] = make_float2(sv.x * inv, xv.x);
                fd[idx * 4 + 1] = make_float2(sv.y * inv, xv.y);
                fd[idx * 4 + 2] = make_float2(sv.z * inv, xv.z);
                fd[idx * 4 + 3] = make_float2(sv.w * inv, xv.w);
            }
        }
        __syncwarp();

        // ---- phase B: 4 nodes x 2 output cols per lane ----
        float2 o0 = make_float2(bl0, bl1), o1 = o0, o2 = o0, o3 = o0;
#pragma unroll 8
        for (int k = 0; k < K; k++) {
            float2 wlv = *(const float2*)&s_wl[(k << 6) + (lid << 1)];
            float2 wrv = *(const float2*)&s_wr[(k << 6) + (lid << 1)];
            float2 f;
            f = *(const float2*)&s_feat[0 * (K * 2) + 2 * k];
            o0.x += f.x * wlv.x + f.y * wrv.x; o0.y += f.x * wlv.y + f.y * wrv.y;
            f = *(const float2*)&s_feat[1 * (K * 2) + 2 * k];
            o1.x += f.x * wlv.x + f.y * wrv.x; o1.y += f.x * wlv.y + f.y * wrv.y;
            f = *(const float2*)&s_feat[2 * (K * 2) + 2 * k];
            o2.x += f.x * wlv.x + f.y * wrv.x; o2.y += f.x * wlv.y + f.y * wrv.y;
            f = *(const float2*)&s_feat[3 * (K * 2) + 2 * k];
            o3.x += f.x * wlv.x + f.y * wrv.x; o3.y += f.x * wlv.y + f.y * wrv.y;
        }
        o0.x = fmaxf(o0.x, 0.f); o0.y = fmaxf(o0.y, 0.f);
        o1.x = fmaxf(o1.x, 0.f); o1.y = fmaxf(o1.y, 0.f);
        o2.x = fmaxf(o2.x, 0.f); o2.y = fmaxf(o2.y, 0.f);
        o3.x = fmaxf(o3.x, 0.f); o3.y = fmaxf(o3.y, 0.f);

        if (!FUSE) {
#pragma unroll
            for (int jj = 0; jj < 4; jj++) {
                int n = n0 + jj;
                if (n < N) {
                    float2 o = jj == 0 ? o0 : jj == 1 ? o1 : jj == 2 ? o2 : o3;
                    float* ot = out + (size_t)n * 64;
                    ot[lid] = o.x; ot[32 + lid] = o.y;
                }
            }
        } else {
            __syncwarp();  // feat reads done before overwriting aliased s_o
            ((float2*)s_o)[0 * 32 + lid] = o0;
            ((float2*)s_o)[1 * 32 + lid] = o1;
            ((float2*)s_o)[2 * 32 + lid] = o2;
            ((float2*)s_o)[3 * 32 + lid] = o3;
            __syncwarp();
            float2 p0 = make_float2(bp0, bp1), p1 = p0, p2 = p0, p3 = p0;
#pragma unroll 8
            for (int k = 0; k < 64; k++) {
                float2 wpv = *(const float2*)&s_wp[(k << 6) + (lid << 1)];
                int ki = 2 * (k & 31) + (k >> 5);
                float v;
                v = s_o[0 * 64 + ki]; p0.x += v * wpv.x; p0.y += v * wpv.y;
                v = s_o[1 * 64 + ki]; p1.x += v * wpv.x; p1.y += v * wpv.y;
                v = s_o[2 * 64 + ki]; p2.x += v * wpv.x; p2.y += v * wpv.y;
                v = s_o[3 * 64 + ki]; p3.x += v * wpv.x; p3.y += v * wpv.y;
            }
#pragma unroll
            for (int jj = 0; jj < 4; jj++) {
                int n = n0 + jj;
                if (n < N) {
                    float2 p = jj == 0 ? p0 : jj == 1 ? p1 : jj == 2 ? p2 : p3;
                    float* ot = out + (size_t)n * 64;
                    ot[lid] = p.x; ot[32 + lid] = p.y;
                }
            }
        }
        __syncwarp();  // protect s_feat before next tile's phase A
    }
}

// ---------------- edge scorer: logit = relu(pa[src] + pm[dst]) . w2 + b2 ----------------
__global__ __launch_bounds__(256) void edge_kernel(
    const int* __restrict__ src, const int* __restrict__ dst,
    const float* __restrict__ pa, const float* __restrict__ pm,
    const float* __restrict__ w2, const float* __restrict__ b2,
    float* __restrict__ out, int E) {
    int t   = blockIdx.x * blockDim.x + threadIdx.x;
    int gw  = t >> 5;
    int lid = t & 31;
    int sub = lid >> 4, off = lid & 15;
    int e = gw * 2 + sub;
    if (e >= E) return;
    int s = __ldg(&src[e]);
    int d = __ldg(&dst[e]);
    float4 A = __ldg((const float4*)pa + (size_t)s * 16 + off);
    float4 M = __ldg((const float4*)pm + (size_t)d * 16 + off);
    float4 W = __ldg((const float4*)w2 + off);
    float p = fmaxf(A.x + M.x, 0.f) * W.x + fmaxf(A.y + M.y, 0.f) * W.y +
              fmaxf(A.z + M.z, 0.f) * W.z + fmaxf(A.w + M.w, 0.f) * W.w;
    p += __shfl_xor_sync(0xffffffffu, p, 8);
    p += __shfl_xor_sync(0xffffffffu, p, 4);
    p += __shfl_xor_sync(0xffffffffu, p, 2);
    p += __shfl_xor_sync(0xffffffffu, p, 1);
    if (off == 0) out[e] = p + __ldg(&b2[0]);
}

// ---------------- launch ----------------
extern "C" void kernel_launch(void* const* d_in, const int* in_sizes, int n_in,
                              void* d_out, int out_size) {
    const float* x_account  = (const float*)d_in[0];
    const float* x_merchant = (const float*)d_in[1];
    const int*   src        = (const int*)d_in[2];
    const int*   dst        = (const int*)d_in[3];
    const float* w1_am_l = (const float*)d_in[4];
    const float* b1_am_l = (const float*)d_in[5];
    const float* w1_am_r = (const float*)d_in[6];
    const float* w1_ma_l = (const float*)d_in[7];
    const float* b1_ma_l = (const float*)d_in[8];
    const float* w1_ma_r = (const float*)d_in[9];
    const float* w2_am_l = (const float*)d_in[10];
    const float* b2_am_l = (const float*)d_in[11];
    const float* w2_am_r = (const float*)d_in[12];
    const float* w2_ma_l = (const float*)d_in[13];
    const float* b2_ma_l = (const float*)d_in[14];
    const float* w2_ma_r = (const float*)d_in[15];
    const float* mlp_w1  = (const float*)d_in[16];
    const float* mlp_b1  = (const float*)d_in[17];
    const float* mlp_w2  = (const float*)d_in[18];
    const float* mlp_b2  = (const float*)d_in[19];
    float* out = (float*)d_out;

    void *p_deg_acc, *p_deg_mer, *p_sa32, *p_sm32, *p_sa64, *p_sm64;
    void *p_acc1, *p_mer1, *p_pa, *p_pm;
    cudaGetSymbolAddress(&p_deg_acc, g_deg_acc);
    cudaGetSymbolAddress(&p_deg_mer, g_deg_mer);
    cudaGetSymbolAddress(&p_sa32, g_sum_a32);
    cudaGetSymbolAddress(&p_sm32, g_sum_m32);
    cudaGetSymbolAddress(&p_sa64, g_sum_a64);
    cudaGetSymbolAddress(&p_sm64, g_sum_m64);
    cudaGetSymbolAddress(&p_acc1, g_acc1);
    cudaGetSymbolAddress(&p_mer1, g_mer1);
    cudaGetSymbolAddress(&p_pa, g_pa);
    cudaGetSymbolAddress(&p_pm, g_pm);

    // raise dynamic smem cap for the 64KB FUSE kernel
    cudaFuncSetAttribute(node_kernel<64, true>,
                         cudaFuncAttributeMaxDynamicSharedMemorySize, 72 * 1024);

    cudaMemsetAsync(p_deg_acc, 0, (size_t)NA * 4, 0);
    cudaMemsetAsync(p_deg_mer, 0, (size_t)NM * 4, 0);
    cudaMemsetAsync(p_sm32, 0, (size_t)NM * FIN * 4, 0);
    cudaMemsetAsync(p_sa32, 0, (size_t)NA * FIN * 4, 0);
    cudaMemsetAsync(p_sm64, 0, (size_t)NM * HH * 4, 0);
    cudaMemsetAsync(p_sa64, 0, (size_t)NA * HH * 4, 0);

    // layer 1 aggregation (FIN=32) + degree folding
    scatter_kernel<32, true><<<31250, 256>>>(src, dst, x_account, (float*)p_sm32,
                                             (float*)p_deg_mer, EDG);
    scatter_kernel<32, true><<<31250, 256>>>(dst, src, x_merchant, (float*)p_sa32,
                                             (float*)p_deg_acc, EDG);

    // layer 1 node transforms
    int smem32 = (2 * 32 * 64 + 8 * 4 * 32 * 2) * 4;
    node_kernel<32, false><<<1184, 256, smem32>>>(
        (const float*)p_sm32, (const float*)p_deg_mer, x_merchant,
        w1_am_l, b1_am_l, w1_am_r, nullptr, nullptr, (float*)p_mer1, NM);
    node_kernel<32, false><<<1184, 256, smem32>>>(
        (const float*)p_sa32, (const float*)p_deg_acc, x_account,
        w1_ma_l, b1_ma_l, w1_ma_r, nullptr, nullptr, (float*)p_acc1, NA);

    // layer 2 aggregation (H=64)
    scatter_kernel<64, false><<<62500, 256>>>(src, dst, (const float*)p_acc1,
                                              (float*)p_sm64, nullptr, EDG);
    scatter_kernel<64, false><<<62500, 256>>>(dst, src, (const float*)p_mer1,
                                              (float*)p_sa64, nullptr, EDG);

    // layer 2 node transforms fused with edge-MLP projection
    int smem64 = (2 * 64 * 64 + 64 * 64 + 8 * 4 * 64 * 2) * 4;
    node_kernel<64, true><<<592, 256, smem64>>>(
        (const float*)p_sm64, (const float*)p_deg_mer, (const float*)p_mer1,
        w2_am_l, b2_am_l, w2_am_r, mlp_w1 + 64 * 64, mlp_b1, (float*)p_pm, NM);
    node_kernel<64, true><<<592, 256, smem64>>>(
        (const float*)p_sa64, (const float*)p_deg_acc, (const float*)p_acc1,
        w2_ma_l, b2_ma_l, w2_ma_r, mlp_w1, nullptr, (float*)p_pa, NA);

    // edge scorer
    edge_kernel<<<62500, 256>>>(src, dst, (const float*)p_pa, (const float*)p_pm,
                                mlp_w2, mlp_b2, out, EDG);
}